// round 4
// baseline (speedup 1.0000x reference)
#include <cuda_runtime.h>

// CustomStrainEnergyLoss: mean over B of (trapz(y_pred - y_true, x, segments j < idx))^2
// Element-weight form: integral = sum_{j=0}^{idx} w(j) * (p[j]-t[j]),
//   w(j) = 0.5*((j>0 ? x[j]-x[j-1] : 0) + (j<idx ? x[j+1]-x[j] : 0))
// Interior (0<=j, j+? handled): w(j) = 0.5*(x[j+1]-x[j-1]) with x[-1] clamped to x[0]
// (clamping reproduces the j=0 weight exactly: 0.5*(x[1]-x[0])).
//
// Clean vector range: v in [0, idx>>2)  ==> all four lanes j=4v..4v+3 satisfy
// j+3 < idx is NOT needed per-lane; precisely 4v+3 < idx for all v < idx>>2,
// so every lane has both neighbors inside [0, idx] and full weight applies.
// Remainder elements [4*(idx>>2), idx] run in a short scalar tail.

#define THREADS 256

__global__ void zero_out_kernel(float* out) {
    out[0] = 0.0f;
}

__global__ __launch_bounds__(THREADS)
void strain_loss_kernel(const float* __restrict__ y_pred,
                        const float* __restrict__ y_true,
                        const float* __restrict__ x,
                        const int* __restrict__ fidx,
                        float* __restrict__ out,
                        int N, float inv_B) {
    const int r = blockIdx.x;
    int idx = fidx[r];
    idx = min(max(idx, 0), N - 1);

    const float* __restrict__ p = y_pred + (size_t)r * N;
    const float* __restrict__ t = y_true + (size_t)r * N;
    const float4* __restrict__ p4 = (const float4*)p;
    const float4* __restrict__ t4 = (const float4*)t;
    const float4* __restrict__ x4 = (const float4*)x;

    // number of clean (fully-interior-weighted) float4 vectors
    const int nc = idx >> 2;

    float acc = 0.0f;

    // Interior loop: central-difference weights, no per-lane predicates.
    // Unrolled for MLP: independent LDG.128s in flight.
    #pragma unroll 4
    for (int v = threadIdx.x; v < nc; v += THREADS) {
        const int j0 = v << 2;
        float4 a  = p4[v];
        float4 b  = t4[v];
        float4 xv = x4[v];                      // x[j0..j0+3]
        float xm1 = x[j0 ? (j0 - 1) : 0];       // clamp: j0==0 -> x[0]
        float xp4 = x[j0 + 4];                  // safe: j0+4 <= idx <= N-1

        acc = fmaf(0.5f * (xv.y - xm1),  a.x - b.x, acc);
        acc = fmaf(0.5f * (xv.z - xv.x), a.y - b.y, acc);
        acc = fmaf(0.5f * (xv.w - xv.y), a.z - b.z, acc);
        acc = fmaf(0.5f * (xp4  - xv.z), a.w - b.w, acc);
    }

    // Scalar tail: elements [4*nc, idx]  (at most 4 elements)
    for (int j = (nc << 2) + threadIdx.x; j <= idx; j += THREADS) {
        float left  = (j > 0)   ? (x[j] - x[j - 1]) : 0.0f;
        float right = (j < idx) ? (x[j + 1] - x[j]) : 0.0f;
        acc = fmaf(0.5f * (left + right), p[j] - t[j], acc);
    }

    // Block reduction: warp shuffle then shared memory
    #pragma unroll
    for (int off = 16; off > 0; off >>= 1)
        acc += __shfl_xor_sync(0xFFFFFFFFu, acc, off);

    __shared__ float warp_sums[THREADS / 32];
    const int lane = threadIdx.x & 31;
    const int wid  = threadIdx.x >> 5;
    if (lane == 0) warp_sums[wid] = acc;
    __syncthreads();

    if (wid == 0) {
        float s = (lane < THREADS / 32) ? warp_sums[lane] : 0.0f;
        #pragma unroll
        for (int off = 4; off > 0; off >>= 1)
            s += __shfl_xor_sync(0xFFFFFFFFu, s, off);
        if (lane == 0) {
            atomicAdd(out, s * s * inv_B);   // err_sq pre-scaled by 1/B
        }
    }
}

extern "C" void kernel_launch(void* const* d_in, const int* in_sizes, int n_in,
                              void* d_out, int out_size) {
    const float* y_pred = (const float*)d_in[0];
    const float* y_true = (const float*)d_in[1];
    const float* x_vals = (const float*)d_in[2];
    const int*   fidx   = (const int*)d_in[3];
    float* out = (float*)d_out;

    const int B = in_sizes[3];   // fracture_idx element count
    const int N = in_sizes[2];   // x_values element count

    zero_out_kernel<<<1, 1>>>(out);
    strain_loss_kernel<<<B, THREADS>>>(y_pred, y_true, x_vals, fidx, out,
                                       N, 1.0f / (float)B);
}